// round 10
// baseline (speedup 1.0000x reference)
#include <cuda_runtime.h>
#include <cstdint>

#define BATCH 16
#define Hn 512
#define Wn 512
#define WPR 16            // 32-bit words per row
#define ST 17             // smem row stride (bank padding)
#define CSIZE 4           // cluster size (CTAs per image)
#define CROWS (Hn / CSIZE)   // 128 rows per CTA
#define AR (CROWS + 4)       // A-buffer rows: own + 2-row halo each side
#define BRR (CROWS + 2)      // B-buffer rows: own + 1-row halo each side
#define NTHR 1024            // 8 threads per row, 2 words each
#define WPT 2

// counting: each of the 8 CTAs per batch counts a 64-row strip (+3 halo)
#define STRIP 64
#define CR (STRIP + 6)

__device__ uint32_t g_skel[2][BATCH][Hn][WPR];
__device__ int g_counts[BATCH][3];     // integer partials (deterministic)
__device__ int g_bt[BATCH];            // per-batch arrival tickets (monotonic)
__device__ int g_ticket;               // finalize ticket (monotonic, &127)

// ---------------------------------------------------------------------------
// helpers
// ---------------------------------------------------------------------------
__device__ __forceinline__ uint32_t smem_u32(const void* p) {
    uint32_t a;
    asm("{ .reg .u64 t; cvta.to.shared.u64 t, %1; cvt.u32.u64 %0, t; }"
        : "=r"(a) : "l"(p));
    return a;
}
__device__ __forceinline__ void st_cluster(uint32_t laddr, uint32_t rank, uint32_t val) {
    asm volatile(
        "{ .reg .b32 ra; mapa.shared::cluster.u32 ra, %0, %1; "
        "st.shared::cluster.u32 [ra], %2; }"
        :: "r"(laddr), "r"(rank), "r"(val) : "memory");
}
__device__ __forceinline__ uint32_t cluster_rank() {
    uint32_t r; asm("mov.u32 %0, %%cluster_ctarank;" : "=r"(r)); return r;
}
#define CLUSTER_SYNC() do { \
    asm volatile("barrier.cluster.arrive.aligned;" ::: "memory"); \
    asm volatile("barrier.cluster.wait.aligned;"   ::: "memory"); \
} while (0)

// One Zhang-Suen sub-step on a 2-word strip given 3x4 word neighborhood.
__device__ __forceinline__ void thin_pair(int sub,
    uint32_t uL, uint32_t u0, uint32_t u1, uint32_t uR,
    uint32_t cL, uint32_t c0, uint32_t c1, uint32_t cR,
    uint32_t dL, uint32_t d0, uint32_t d1, uint32_t dR,
    uint32_t out[WPT])
{
    #pragma unroll
    for (int w = 0; w < WPT; ++w) {
        uint32_t aP = w ? u0 : uL, aC = w ? u1 : u0, aN = w ? uR : u1;
        uint32_t cP = w ? c0 : cL, cC = w ? c1 : c0, cN = w ? cR : c1;
        uint32_t bP = w ? d0 : dL, bC = w ? d1 : d0, bN = w ? dR : d1;

        uint32_t n0 = aC;
        uint32_t n1 = (aC >> 1) | (aN << 31);
        uint32_t n2 = (cC >> 1) | (cN << 31);
        uint32_t n3 = (bC >> 1) | (bN << 31);
        uint32_t n4 = bC;
        uint32_t n5 = (bC << 1) | (bP >> 31);
        uint32_t n6 = (cC << 1) | (cP >> 31);
        uint32_t n7 = (aC << 1) | (aP >> 31);

        // A == 1
        uint32_t e0 = ~n0 & n1, e1 = ~n1 & n2, e2 = ~n2 & n3, e3 = ~n3 & n4;
        uint32_t e4 = ~n4 & n5, e5 = ~n5 & n6, e6 = ~n6 & n7, e7 = ~n7 & n0;
        uint32_t one = e0, more = 0;
        more |= one & e1; one |= e1;
        more |= one & e2; one |= e2;
        more |= one & e3; one |= e3;
        more |= one & e4; one |= e4;
        more |= one & e5; one |= e5;
        more |= one & e6; one |= e6;
        more |= one & e7; one |= e7;
        uint32_t A1 = one & ~more;

        // Bn >= 2
        uint32_t o2 = n0, m2 = 0;
        m2 |= o2 & n1; o2 |= n1;
        m2 |= o2 & n2; o2 |= n2;
        m2 |= o2 & n3; o2 |= n3;
        m2 |= o2 & n4; o2 |= n4;
        m2 |= o2 & n5; o2 |= n5;
        m2 |= o2 & n6; o2 |= n6;
        m2 |= o2 & n7; o2 |= n7;
        uint32_t ge2 = m2;

        // Bn <= 6 (>=2 neighbors zero)
        uint32_t z, oz = ~n0, mz = 0;
        z = ~n1; mz |= oz & z; oz |= z;
        z = ~n2; mz |= oz & z; oz |= z;
        z = ~n3; mz |= oz & z; oz |= z;
        z = ~n4; mz |= oz & z; oz |= z;
        z = ~n5; mz |= oz & z; oz |= z;
        z = ~n6; mz |= oz & z; oz |= z;
        z = ~n7; mz |= oz & z; oz |= z;
        uint32_t le6 = mz;

        uint32_t cond = A1 & ge2 & le6;
        if (sub == 0)
            cond &= ~(n0 & n2 & n4) & ~(n2 & n4 & n6);
        else
            cond &= ~(n0 & n2 & n6) & ~(n0 & n4 & n6);

        out[w] = cC & ~cond;
    }
}

// load 4-word neighborhood row (L, w0, w1, R) from smem row base
#define ROW4(base, wb, L, W0, W1, RR) do { \
    L  = (wb) ? (base)[(wb) - 1] : 0u; \
    W0 = (base)[(wb)]; \
    W1 = (base)[(wb) + 1]; \
    RR = ((wb) < 14) ? (base)[(wb) + 2] : 0u; \
} while (0)

// horizontal dilations on an ST-strided window (counting stage)
__device__ __forceinline__ uint32_t hd3(const uint32_t* M, int r, int w) {
    uint32_t p = (w > 0)       ? M[r * ST + w - 1] : 0u;
    uint32_t c =                 M[r * ST + w];
    uint32_t n = (w < WPR - 1) ? M[r * ST + w + 1] : 0u;
    uint32_t v = c;
    v |= (c >> 1) | (n << 31); v |= (c << 1) | (p >> 31);
    v |= (c >> 2) | (n << 30); v |= (c << 2) | (p >> 30);
    v |= (c >> 3) | (n << 29); v |= (c << 3) | (p >> 29);
    return v;
}
__device__ __forceinline__ uint32_t hd2(const uint32_t* M, int r, int w) {
    uint32_t p = (w > 0)       ? M[r * ST + w - 1] : 0u;
    uint32_t c =                 M[r * ST + w];
    uint32_t n = (w < WPR - 1) ? M[r * ST + w + 1] : 0u;
    uint32_t v = c;
    v |= (c >> 1) | (n << 31); v |= (c << 1) | (p >> 31);
    v |= (c >> 2) | (n << 30); v |= (c << 2) | (p >> 30);
    return v;
}
__device__ __forceinline__ uint32_t dil3w(const uint32_t* M, int r, int w) {
    uint32_t v = hd3(M, r, w);
    v |= hd2(M, r - 1, w) | hd2(M, r + 1, w);
    v |= hd2(M, r - 2, w) | hd2(M, r + 2, w);
    v |= M[(r - 3) * ST + w] | M[(r + 3) * ST + w];
    return v;
}

// ---------------------------------------------------------------------------
// Fused kernel: binarize + Zhang-Suen to convergence with ONE cluster sync
// per full iteration (sub0+sub1 temporally blocked, 2-row halo), then
// parallel per-strip counting after a per-batch spin rendezvous.
// ---------------------------------------------------------------------------
__global__ void __launch_bounds__(NTHR, 1) __cluster_dims__(CSIZE, 1, 1)
skel_kernel(const float* __restrict__ pred, const float* __restrict__ gt,
            float* __restrict__ out) {
    __shared__ uint32_t A[2][AR * ST];     // ping-pong, rows -2..129 (idx+2)
    __shared__ uint32_t Bb[BRR * ST];      // intermediate sub0, rows -1..128 (idx+1)
    __shared__ int s_chg[2][AR];           // per-row change stamp by parity (idx+2)
    __shared__ int s_changed;              // local max change stamp
    __shared__ int c_changed;              // cluster max change stamp
    __shared__ int stp, sfp, sfn;

    const int tid = threadIdx.x;
    const uint32_t rank = cluster_rank();
    const int img = blockIdx.x >> 2;
    const int b = img & 15;
    const int m = img >> 4;          // 0 = pred, 1 = gt
    const float* in = (m ? gt : pred) + (size_t)b * Hn * Wn + (size_t)rank * CROWS * Wn;

    // init stamps, flags, halo rows
    if (tid < AR) { s_chg[0][tid] = 0; s_chg[1][tid] = 0; }
    if (tid == 0) { s_changed = 0; c_changed = 0; }
    if (tid < 2 * 4 * WPR) {          // A halos: 2 bufs x rows {0,1,AR-2,AR-1}
        int bi = tid >> 6, rs = (tid >> 4) & 3, w = tid & 15;
        int r = (rs < 2) ? rs : (AR - 4 + rs);
        A[bi][r * ST + w] = 0;
    }
    if (tid >= 128 && tid < 128 + 2 * WPR) {   // B halos: rows {0, BRR-1}
        int rs = (tid >> 4) & 1, w = tid & 15;
        Bb[(rs ? (BRR - 1) : 0) * ST + w] = 0;
    }

    // --- binarize own 128 rows into A[1] (iteration 1 reads A[1]) ---
    #pragma unroll 4
    for (int p = 0; p < (CROWS * Wn) / NTHR; ++p) {
        int idx = p * NTHR + tid;
        float v = in[idx];
        uint32_t bits = __ballot_sync(0xffffffffu, v > 0.5f);
        if ((tid & 31) == 0) {
            int r = idx >> 9;
            int w = (idx >> 5) & 15;
            A[1][(r + 2) * ST + w] = bits;
        }
    }
    __syncthreads();

    const int lrow  = tid >> 3;          // 0..127
    const int q     = tid & 7;
    const int wbase = q * WPT;
    const int ia    = lrow + 2;          // A row index
    const int ib    = lrow + 1;          // B row index
    const bool topB = (lrow <= 1)           && (rank > 0);
    const bool botB = (lrow >= CROWS - 2)   && (rank < CSIZE - 1);

    uint32_t R[WPT];
    R[0] = A[1][ia * ST + wbase];
    R[1] = A[1][ia * ST + wbase + 1];

    int t = 0;
    int myLast = 0;

    for (;;) {
        ++t;
        uint32_t* cur = A[t & 1];

        // ---- store phase: own words + 2-row halo pushes ----
        if (myLast > t - 3) {
            cur[ia * ST + wbase]     = R[0];
            cur[ia * ST + wbase + 1] = R[1];
            if (topB) {   // my rows 0,1 -> upper neighbor rows 128,129 (idx 130,131)
                uint32_t d = smem_u32(&cur[(AR - 2 + lrow) * ST + wbase]);
                st_cluster(d,     rank - 1, R[0]);
                st_cluster(d + 4, rank - 1, R[1]);
            }
            if (botB) {   // my rows 126,127 -> lower neighbor rows -2,-1 (idx 0,1)
                uint32_t d = smem_u32(&cur[(lrow - (CROWS - 2)) * ST + wbase]);
                st_cluster(d,     rank + 1, R[0]);
                st_cluster(d + 4, rank + 1, R[1]);
            }
        }
        // push prev-iteration stamps for boundary rows
        if (q == 0) {
            const int pp = (t - 1) & 1;
            int stamp = s_chg[pp][ia];
            if (topB) st_cluster(smem_u32(&s_chg[pp][AR - 2 + lrow]), rank - 1, (uint32_t)stamp);
            if (botB) st_cluster(smem_u32(&s_chg[pp][lrow - (CROWS - 2)]), rank + 1, (uint32_t)stamp);
        }
        // broadcast "changed at t-1"
        if (tid == 0 && s_changed == t - 1) {
            uint32_t a = smem_u32(&c_changed);
            #pragma unroll
            for (int c = 0; c < CSIZE; ++c) st_cluster(a, c, (uint32_t)(t - 1));
        }
        CLUSTER_SYNC();

        if (c_changed <= t - 2) break;    // previous full iteration: no change

        // ---- dirty check (influence radius 2 per iteration) ----
        const int pp = (t - 1) & 1, ps = t - 1;
        bool dirty = (s_chg[pp][ia - 2] == ps) | (s_chg[pp][ia - 1] == ps) |
                     (s_chg[pp][ia]     == ps) | (s_chg[pp][ia + 1] == ps) |
                     (s_chg[pp][ia + 2] == ps);

        uint32_t Breg[WPT];
        if (dirty) {
            // ---- sub0 for own row (center from registers) ----
            const uint32_t* rU = cur + (ia - 1) * ST;
            const uint32_t* rC = cur + ia * ST;
            const uint32_t* rD = cur + (ia + 1) * ST;
            uint32_t uL, u0, u1, uR, dL, d0, d1, dR, cL, cR;
            ROW4(rU, wbase, uL, u0, u1, uR);
            ROW4(rD, wbase, dL, d0, d1, dR);
            cL = wbase ? rC[wbase - 1] : 0u;
            cR = (wbase < 14) ? rC[wbase + 2] : 0u;
            thin_pair(0, uL, u0, u1, uR, cL, R[0], R[1], cR, dL, d0, d1, dR, Breg);
            Bb[ib * ST + wbase]     = Breg[0];
            Bb[ib * ST + wbase + 1] = Breg[1];
        }
        // ---- sub0 for halo rows (-1 / 128) by boundary-row threads ----
        if (lrow == 0 && rank > 0) {
            bool hd = (s_chg[pp][0] == ps) | (s_chg[pp][1] == ps) | (s_chg[pp][2] == ps);
            if (hd) {
                uint32_t uL, u0, u1, uR, cL, c0, c1, cR, dL, d0, d1, dR, o[WPT];
                ROW4(cur + 0 * ST, wbase, uL, u0, u1, uR);
                ROW4(cur + 1 * ST, wbase, cL, c0, c1, cR);
                ROW4(cur + 2 * ST, wbase, dL, d0, d1, dR);
                thin_pair(0, uL, u0, u1, uR, cL, c0, c1, cR, dL, d0, d1, dR, o);
                Bb[0 * ST + wbase] = o[0]; Bb[0 * ST + wbase + 1] = o[1];
            }
        }
        if (lrow == CROWS - 1 && rank < CSIZE - 1) {
            bool hd = (s_chg[pp][AR - 3] == ps) | (s_chg[pp][AR - 2] == ps) | (s_chg[pp][AR - 1] == ps);
            if (hd) {
                uint32_t uL, u0, u1, uR, cL, c0, c1, cR, dL, d0, d1, dR, o[WPT];
                ROW4(cur + (AR - 3) * ST, wbase, uL, u0, u1, uR);
                ROW4(cur + (AR - 2) * ST, wbase, cL, c0, c1, cR);
                ROW4(cur + (AR - 1) * ST, wbase, dL, d0, d1, dR);
                thin_pair(0, uL, u0, u1, uR, cL, c0, c1, cR, dL, d0, d1, dR, o);
                Bb[(BRR - 1) * ST + wbase] = o[0]; Bb[(BRR - 1) * ST + wbase + 1] = o[1];
            }
        }
        __syncthreads();   // B complete

        if (dirty) {
            // ---- sub1 for own row (center = Breg) ----
            const uint32_t* bU = Bb + (ib - 1) * ST;
            const uint32_t* bC = Bb + ib * ST;
            const uint32_t* bD = Bb + (ib + 1) * ST;
            uint32_t uL, u0, u1, uR, dL, d0, d1, dR, cL, cR, o[WPT];
            ROW4(bU, wbase, uL, u0, u1, uR);
            ROW4(bD, wbase, dL, d0, d1, dR);
            cL = wbase ? bC[wbase - 1] : 0u;
            cR = (wbase < 14) ? bC[wbase + 2] : 0u;
            thin_pair(1, uL, u0, u1, uR, cL, Breg[0], Breg[1], cR, dL, d0, d1, dR, o);

            uint32_t removed = (R[0] ^ o[0]) | (R[1] ^ o[1]);
            R[0] = o[0]; R[1] = o[1];
            if (removed) {
                s_chg[t & 1][ia] = t;
                s_changed = t;
                myLast = t;
            }
        }
    }

    // ---- write out bit-packed skeleton from registers ----
    const int grow = (int)rank * CROWS + lrow;
    g_skel[m][b][grow][wbase]     = R[0];
    g_skel[m][b][grow][wbase + 1] = R[1];

    // ---- per-batch rendezvous (8 CTAs per batch) ----
    __threadfence();
    __syncthreads();
    if (tid == 0) {
        if (m == 0 && rank == 0) {
            g_counts[b][0] = 0; g_counts[b][1] = 0; g_counts[b][2] = 0;
            __threadfence();
        }
        atomicAdd(&g_bt[b], 1);
        while ((((volatile int*)g_bt)[b] & 7) != 0) __nanosleep(64);
        __threadfence();
    }
    __syncthreads();

    // ---- parallel counting: this CTA counts a 64-row strip of batch b ----
    const int cidx = m * CSIZE + (int)rank;     // 0..7
    const int base = cidx * STRIP - 3;
    uint32_t* sP = &A[0][0];                    // reuse smem (CR*ST fits)
    uint32_t* sG = &A[1][0];
    const uint32_t* P = &g_skel[0][b][0][0];
    const uint32_t* G = &g_skel[1][b][0][0];

    for (int idx = tid; idx < CR * WPR; idx += NTHR) {
        int r = idx >> 4, w = idx & 15;
        int gr = base + r;
        bool ok = (gr >= 0) & (gr < Hn);
        sP[r * ST + w] = ok ? P[gr * WPR + w] : 0u;
        sG[r * ST + w] = ok ? G[gr * WPR + w] : 0u;
    }
    __syncthreads();

    const int rl = (tid >> 4) + 3;
    const int wc = tid & 15;
    uint32_t dg = dil3w(sG, rl, wc);
    uint32_t dp = dil3w(sP, rl, wc);
    uint32_t pw = sP[rl * ST + wc];
    uint32_t gw = sG[rl * ST + wc];
    int tp = __popc(pw & dg);
    int fp = __popc(pw & ~dg);
    int fn = __popc(gw & ~dp);

    if (tid == 0) { stp = 0; sfp = 0; sfn = 0; }
    __syncthreads();
    #pragma unroll
    for (int o = 16; o > 0; o >>= 1) {
        tp += __shfl_down_sync(0xffffffffu, tp, o);
        fp += __shfl_down_sync(0xffffffffu, fp, o);
        fn += __shfl_down_sync(0xffffffffu, fn, o);
    }
    if ((tid & 31) == 0) {
        atomicAdd(&stp, tp);
        atomicAdd(&sfp, fp);
        atomicAdd(&sfn, fn);
    }
    __syncthreads();

    if (tid == 0) {
        atomicAdd(&g_counts[b][0], stp);
        atomicAdd(&g_counts[b][1], sfp);
        atomicAdd(&g_counts[b][2], sfn);
        __threadfence();
        int tk = atomicAdd(&g_ticket, 1) & 127;
        if (tk == 127) {
            __threadfence();
            float s0 = 0.f, s1 = 0.f, s2 = 0.f;
            for (int bb = 0; bb < BATCH; ++bb) {
                float TP = (float)g_counts[bb][0];
                float FP = (float)g_counts[bb][1];
                float FN = (float)g_counts[bb][2];
                s0 += TP / (TP + FP + 1e-12f);
                s1 += TP / (TP + FN + 1e-12f);
                s2 += TP / (TP + FP + FN + 1e-12f);
            }
            out[0] = s0 * (1.0f / BATCH);
            out[1] = s1 * (1.0f / BATCH);
            out[2] = s2 * (1.0f / BATCH);
        }
    }
}

extern "C" void kernel_launch(void* const* d_in, const int* in_sizes, int n_in,
                              void* d_out, int out_size) {
    (void)in_sizes; (void)n_in; (void)out_size;
    const float* pred = (const float*)d_in[0];
    const float* gt   = (const float*)d_in[1];
    skel_kernel<<<2 * BATCH * CSIZE, NTHR>>>(pred, gt, (float*)d_out);
}

// round 11
// speedup vs baseline: 1.0229x; 1.0229x over previous
#include <cuda_runtime.h>
#include <cstdint>

#define BATCH 16
#define Hn 512
#define Wn 512
#define WPR 16            // 32-bit words per row
#define ST 17             // smem row stride (bank padding)
#define CSIZE 8           // cluster size (CTAs per image)
#define CROWS (Hn / CSIZE)   // 64 rows per CTA
#define BR (CROWS + 2)       // rows incl. top/bottom halo
#define NTHR 512             // 8 threads per row, 2 words each
#define WPT 2

// counting: each of the 16 CTAs per batch counts a 32-row strip (+3 halo)
#define STRIP 32
#define CR (STRIP + 6)       // 38-row window

__device__ uint32_t g_skel[2][BATCH][Hn][WPR];
__device__ int g_counts[BATCH][3];     // integer partials (deterministic)
__device__ int g_bt[BATCH];            // per-batch arrival tickets (monotonic)
__device__ int g_ticket;               // finalize ticket (monotonic, &255)

// ---------------------------------------------------------------------------
// helpers
// ---------------------------------------------------------------------------
__device__ __forceinline__ uint32_t smem_u32(const void* p) {
    uint32_t a;
    asm("{ .reg .u64 t; cvta.to.shared.u64 t, %1; cvt.u32.u64 %0, t; }"
        : "=r"(a) : "l"(p));
    return a;
}
__device__ __forceinline__ void st_cluster(uint32_t laddr, uint32_t rank, uint32_t val) {
    asm volatile(
        "{ .reg .b32 ra; mapa.shared::cluster.u32 ra, %0, %1; "
        "st.shared::cluster.u32 [ra], %2; }"
        :: "r"(laddr), "r"(rank), "r"(val) : "memory");
}
__device__ __forceinline__ uint32_t cluster_rank() {
    uint32_t r; asm("mov.u32 %0, %%cluster_ctarank;" : "=r"(r)); return r;
}
#define CLUSTER_SYNC() do { \
    asm volatile("barrier.cluster.arrive.aligned;" ::: "memory"); \
    asm volatile("barrier.cluster.wait.aligned;"   ::: "memory"); \
} while (0)

// horizontal dilations on an ST-strided window
__device__ __forceinline__ uint32_t hd3(const uint32_t* M, int r, int w) {
    uint32_t p = (w > 0)       ? M[r * ST + w - 1] : 0u;
    uint32_t c =                 M[r * ST + w];
    uint32_t n = (w < WPR - 1) ? M[r * ST + w + 1] : 0u;
    uint32_t v = c;
    v |= (c >> 1) | (n << 31); v |= (c << 1) | (p >> 31);
    v |= (c >> 2) | (n << 30); v |= (c << 2) | (p >> 30);
    v |= (c >> 3) | (n << 29); v |= (c << 3) | (p >> 29);
    return v;
}
__device__ __forceinline__ uint32_t hd2(const uint32_t* M, int r, int w) {
    uint32_t p = (w > 0)       ? M[r * ST + w - 1] : 0u;
    uint32_t c =                 M[r * ST + w];
    uint32_t n = (w < WPR - 1) ? M[r * ST + w + 1] : 0u;
    uint32_t v = c;
    v |= (c >> 1) | (n << 31); v |= (c << 1) | (p >> 31);
    v |= (c >> 2) | (n << 30); v |= (c << 2) | (p >> 30);
    return v;
}
__device__ __forceinline__ uint32_t dil3w(const uint32_t* M, int r, int w) {
    // squared radius 9: dy=0 -> |dx|<=3; |dy| in {1,2} -> |dx|<=2; |dy|=3 -> dx=0
    uint32_t v = hd3(M, r, w);
    v |= hd2(M, r - 1, w) | hd2(M, r + 1, w);
    v |= hd2(M, r - 2, w) | hd2(M, r + 2, w);
    v |= M[(r - 3) * ST + w] | M[(r + 3) * ST + w];
    return v;
}

// ---------------------------------------------------------------------------
// Fused kernel: binarize + Zhang-Suen to convergence (8-CTA cluster per
// image, 2 CTAs/SM so cluster-barrier waits overlap with the co-resident
// CTA's compute), then parallel per-strip counting after a per-batch
// spin rendezvous.
// ---------------------------------------------------------------------------
__global__ void __launch_bounds__(NTHR, 2) __cluster_dims__(CSIZE, 1, 1)
skel_kernel(const float* __restrict__ pred, const float* __restrict__ gt,
            float* __restrict__ out) {
    __shared__ uint32_t bufs[2][BR * ST];
    __shared__ int s_chg[2][BR];     // stamp of last change per row, by parity
    __shared__ int s_changed;        // local: max stamp with any removal
    __shared__ int c_changed;        // cluster: max stamp with any removal
    __shared__ int stp, sfp, sfn;

    const int tid = threadIdx.x;
    const uint32_t rank = cluster_rank();
    const int img = blockIdx.x >> 3;     // 8 CTAs per image
    const int b = img & 15;
    const int m = img >> 4;              // 0 = pred, 1 = gt
    const float* in = (m ? gt : pred) + (size_t)b * Hn * Wn + (size_t)rank * CROWS * Wn;

    // init stamps, flags, halo rows (halos stay 0 forever on image edges)
    if (tid < BR) { s_chg[0][tid] = 0; s_chg[1][tid] = 0; }
    if (tid == 0) { s_changed = 0; c_changed = 0; }
    if (tid < 2 * 2 * WPR) {          // 64 halo words: 2 bufs x {row 0, row BR-1}
        int bi = tid >> 5, r = (tid >> 4) & 1, w = tid & 15;
        bufs[bi][(r ? (BR - 1) : 0) * ST + w] = 0;
    }

    // --- binarize own 64 rows into bufs[0] (warp ballots -> packed words) ---
    #pragma unroll 4
    for (int p = 0; p < (CROWS * Wn) / NTHR; ++p) {
        int idx = p * NTHR + tid;
        float v = in[idx];
        uint32_t bits = __ballot_sync(0xffffffffu, v > 0.5f);
        if ((tid & 31) == 0) {
            int r = idx >> 9;            // local row
            int w = (idx >> 5) & 15;
            bufs[0][(r + 1) * ST + w] = bits;
        }
    }
    __syncthreads();

    const int lrow  = tid >> 3;          // 0..63
    const int q     = tid & 7;
    const int wbase = q * WPT;
    const int i     = lrow + 1;          // buffer row index (1..64)
    const bool topB = (lrow == 0)        && (rank > 0);
    const bool botB = (lrow == CROWS-1)  && (rank < CSIZE - 1);

    uint32_t R[WPT];
    #pragma unroll
    for (int w = 0; w < WPT; ++w) R[w] = bufs[0][i * ST + wbase + w];

    int s = 0;
    int myLast = 0;

    for (;;) {
        ++s;
        uint32_t* cur = bufs[s & 1];
        __syncthreads();                 // (A) order prior compute's s_chg writes

        // ---- store phase ----
        if (myLast > s - 3) {
            #pragma unroll
            for (int w = 0; w < WPT; ++w) cur[i * ST + wbase + w] = R[w];
            if (topB) {
                #pragma unroll
                for (int w = 0; w < WPT; ++w)
                    st_cluster(smem_u32(&cur[(BR - 1) * ST + wbase + w]), rank - 1, R[w]);
            }
            if (botB) {
                #pragma unroll
                for (int w = 0; w < WPT; ++w)
                    st_cluster(smem_u32(&cur[0 * ST + wbase + w]), rank + 1, R[w]);
            }
        }
        // transmit own-row stamp of previous sub-iteration to neighbor halo
        if (q == 0) {
            const int pp = (s - 1) & 1;
            int stamp = s_chg[pp][i];
            if (topB) st_cluster(smem_u32(&s_chg[pp][BR - 1]), rank - 1, (uint32_t)stamp);
            if (botB) st_cluster(smem_u32(&s_chg[pp][0]),      rank + 1, (uint32_t)stamp);
        }
        // broadcast "changed at s-1" to all CTAs of the cluster
        if (tid == 0 && s_changed == s - 1) {
            uint32_t a = smem_u32(&c_changed);
            #pragma unroll
            for (int c = 0; c < CSIZE; ++c) st_cluster(a, c, (uint32_t)(s - 1));
        }
        CLUSTER_SYNC();                  // (B)

        if (c_changed <= s - 3) break;   // no removal in sub-iters s-1, s-2

        // ---- compute phase ----
        const int pb = (s - 1) & 1, ps = s - 1;
        bool dirty = (s_chg[pb][i] == ps) | (s_chg[pb][i - 1] == ps) | (s_chg[pb][i + 1] == ps);
        if (!dirty) continue;

        const int sub = (s + 1) & 1;     // s odd -> sub 0 ; s even -> sub 1
        const uint32_t* rU = &cur[(i - 1) * ST];
        const uint32_t* rO = &cur[i * ST];
        const uint32_t* rD = &cur[(i + 1) * ST];

        uint32_t aP = wbase ? rU[wbase - 1] : 0u;
        uint32_t cP = wbase ? rO[wbase - 1] : 0u;
        uint32_t bP = wbase ? rD[wbase - 1] : 0u;
        uint32_t aC = rU[wbase];
        uint32_t cC = R[0];
        uint32_t bC = rD[wbase];
        uint32_t cRight = (q < 7) ? rO[wbase + WPT] : 0u;

        uint32_t removed = 0;
        uint32_t nR[WPT];
        #pragma unroll
        for (int w = 0; w < WPT; ++w) {
            const int gw = wbase + w;
            uint32_t aN = 0, bN = 0, cN;
            if (gw < WPR - 1) { aN = rU[gw + 1]; bN = rD[gw + 1]; }
            cN = (w < WPT - 1) ? R[w + 1] : cRight;

            // P2..P9 clockwise from North
            uint32_t n0 = aC;
            uint32_t n1 = (aC >> 1) | (aN << 31);
            uint32_t n2 = (cC >> 1) | (cN << 31);
            uint32_t n3 = (bC >> 1) | (bN << 31);
            uint32_t n4 = bC;
            uint32_t n5 = (bC << 1) | (bP >> 31);
            uint32_t n6 = (cC << 1) | (cP >> 31);
            uint32_t n7 = (aC << 1) | (aP >> 31);

            // A == 1 (exactly one 0->1 transition around the ring)
            uint32_t e0 = ~n0 & n1, e1 = ~n1 & n2, e2 = ~n2 & n3, e3 = ~n3 & n4;
            uint32_t e4 = ~n4 & n5, e5 = ~n5 & n6, e6 = ~n6 & n7, e7 = ~n7 & n0;
            uint32_t one = e0, more = 0;
            more |= one & e1; one |= e1;
            more |= one & e2; one |= e2;
            more |= one & e3; one |= e3;
            more |= one & e4; one |= e4;
            more |= one & e5; one |= e5;
            more |= one & e6; one |= e6;
            more |= one & e7; one |= e7;
            uint32_t A1 = one & ~more;

            // Bn >= 2
            uint32_t o2 = n0, m2 = 0;
            m2 |= o2 & n1; o2 |= n1;
            m2 |= o2 & n2; o2 |= n2;
            m2 |= o2 & n3; o2 |= n3;
            m2 |= o2 & n4; o2 |= n4;
            m2 |= o2 & n5; o2 |= n5;
            m2 |= o2 & n6; o2 |= n6;
            m2 |= o2 & n7; o2 |= n7;
            uint32_t ge2 = m2;

            // Bn <= 6 (at least 2 neighbors zero)
            uint32_t z, oz = ~n0, mz = 0;
            z = ~n1; mz |= oz & z; oz |= z;
            z = ~n2; mz |= oz & z; oz |= z;
            z = ~n3; mz |= oz & z; oz |= z;
            z = ~n4; mz |= oz & z; oz |= z;
            z = ~n5; mz |= oz & z; oz |= z;
            z = ~n6; mz |= oz & z; oz |= z;
            z = ~n7; mz |= oz & z; oz |= z;
            uint32_t le6 = mz;

            uint32_t cond = A1 & ge2 & le6;
            if (sub == 0)
                cond &= ~(n0 & n2 & n4) & ~(n2 & n4 & n6);
            else
                cond &= ~(n0 & n2 & n6) & ~(n0 & n4 & n6);

            removed |= cC & cond;
            nR[w] = cC & ~cond;

            aP = aC; aC = aN;
            cP = cC; cC = cN;
            bP = bC; bC = bN;
        }
        #pragma unroll
        for (int w = 0; w < WPT; ++w) R[w] = nR[w];
        if (removed) {
            s_chg[s & 1][i] = s;
            s_changed = s;
            myLast = s;
        }
    }

    // ---- write out bit-packed skeleton from registers ----
    const int grow = (int)rank * CROWS + lrow;
    #pragma unroll
    for (int w = 0; w < WPT; ++w)
        g_skel[m][b][grow][wbase + w] = R[w];

    // ---- per-batch rendezvous (16 CTAs per batch: 2 masks x 8 ranks) ----
    __threadfence();
    __syncthreads();                      // all skeleton stores issued + fenced
    if (tid == 0) {
        if (m == 0 && rank == 0) {        // designated zeroer for this batch
            g_counts[b][0] = 0; g_counts[b][1] = 0; g_counts[b][2] = 0;
            __threadfence();
        }
        atomicAdd(&g_bt[b], 1);           // monotonic across graph replays
        while ((((volatile int*)g_bt)[b] & 15) != 0) __nanosleep(64);
        __threadfence();                  // acquire: see all 16 CTAs' writes
    }
    __syncthreads();

    // ---- parallel counting: this CTA counts a 32-row strip of batch b ----
    const int cidx = m * CSIZE + (int)rank;     // 0..15
    const int base = cidx * STRIP - 3;
    uint32_t* sP = &bufs[0][0];                 // reuse smem (CR*ST <= BR*ST)
    uint32_t* sG = &bufs[1][0];
    const uint32_t* P = &g_skel[0][b][0][0];
    const uint32_t* G = &g_skel[1][b][0][0];

    for (int idx = tid; idx < CR * WPR; idx += NTHR) {
        int r = idx >> 4, w = idx & 15;
        int gr = base + r;
        bool ok = (gr >= 0) & (gr < Hn);
        sP[r * ST + w] = ok ? P[gr * WPR + w] : 0u;
        sG[r * ST + w] = ok ? G[gr * WPR + w] : 0u;
    }
    __syncthreads();

    // 32 rows x 16 words = 512 elements: exactly one per thread
    const int rl = (tid >> 4) + 3;      // window row 3..34
    const int wc = tid & 15;
    uint32_t dg = dil3w(sG, rl, wc);
    uint32_t dp = dil3w(sP, rl, wc);
    uint32_t pw = sP[rl * ST + wc];
    uint32_t gw = sG[rl * ST + wc];
    int tp = __popc(pw & dg);
    int fp = __popc(pw & ~dg);
    int fn = __popc(gw & ~dp);

    if (tid == 0) { stp = 0; sfp = 0; sfn = 0; }
    __syncthreads();
    #pragma unroll
    for (int o = 16; o > 0; o >>= 1) {
        tp += __shfl_down_sync(0xffffffffu, tp, o);
        fp += __shfl_down_sync(0xffffffffu, fp, o);
        fn += __shfl_down_sync(0xffffffffu, fn, o);
    }
    if ((tid & 31) == 0) {
        atomicAdd(&stp, tp);
        atomicAdd(&sfp, fp);
        atomicAdd(&sfn, fn);
    }
    __syncthreads();

    if (tid == 0) {
        atomicAdd(&g_counts[b][0], stp);
        atomicAdd(&g_counts[b][1], sfp);
        atomicAdd(&g_counts[b][2], sfn);
        __threadfence();
        int t = atomicAdd(&g_ticket, 1) & 255;   // 256 CTAs total
        if (t == 255) {                           // last CTA finalizes
            __threadfence();
            float s0 = 0.f, s1 = 0.f, s2 = 0.f;
            for (int bb = 0; bb < BATCH; ++bb) {
                float TP = (float)g_counts[bb][0];
                float FP = (float)g_counts[bb][1];
                float FN = (float)g_counts[bb][2];
                s0 += TP / (TP + FP + 1e-12f);
                s1 += TP / (TP + FN + 1e-12f);
                s2 += TP / (TP + FP + FN + 1e-12f);
            }
            out[0] = s0 * (1.0f / BATCH);
            out[1] = s1 * (1.0f / BATCH);
            out[2] = s2 * (1.0f / BATCH);
        }
    }
}

extern "C" void kernel_launch(void* const* d_in, const int* in_sizes, int n_in,
                              void* d_out, int out_size) {
    (void)in_sizes; (void)n_in; (void)out_size;
    const float* pred = (const float*)d_in[0];
    const float* gt   = (const float*)d_in[1];
    skel_kernel<<<2 * BATCH * CSIZE, NTHR>>>(pred, gt, (float*)d_out);
}

// round 12
// speedup vs baseline: 1.0239x; 1.0010x over previous
#include <cuda_runtime.h>
#include <cstdint>

#define BATCH 16
#define Hn 512
#define Wn 512
#define WPR 16            // 32-bit words per row
#define ST 17             // smem row stride (bank padding)
#define CSIZE 4           // cluster size (CTAs per image)
#define CROWS (Hn / CSIZE)   // 128 rows per CTA
#define BR (CROWS + 2)       // rows incl. top/bottom halo
#define NTHR 1024            // 8 threads per row, 2 words each
#define WPT 2

// counting: each of the 8 CTAs per batch counts a 64-row strip (+3 halo)
#define STRIP 64
#define CR (STRIP + 6)

__device__ uint32_t g_skel[2][BATCH][Hn][WPR];
__device__ int g_counts[BATCH][3];     // integer partials (deterministic)
__device__ int g_bt[BATCH];            // per-batch arrival tickets (monotonic)
__device__ int g_ticket;               // finalize ticket (monotonic, &127)

// full adder: s = a^b^c, co = majority(a,b,c)  (2 LOP3s)
#define FA(s, co, a, b, c) do { \
    uint32_t _a = (a), _b = (b), _c = (c); \
    (s)  = _a ^ _b ^ _c; \
    (co) = (_a & _b) | ((_a ^ _b) & _c); \
} while (0)

// ---------------------------------------------------------------------------
// helpers
// ---------------------------------------------------------------------------
__device__ __forceinline__ uint32_t smem_u32(const void* p) {
    uint32_t a;
    asm("{ .reg .u64 t; cvta.to.shared.u64 t, %1; cvt.u32.u64 %0, t; }"
        : "=r"(a) : "l"(p));
    return a;
}
__device__ __forceinline__ void st_cluster(uint32_t laddr, uint32_t rank, uint32_t val) {
    asm volatile(
        "{ .reg .b32 ra; mapa.shared::cluster.u32 ra, %0, %1; "
        "st.shared::cluster.u32 [ra], %2; }"
        :: "r"(laddr), "r"(rank), "r"(val) : "memory");
}
__device__ __forceinline__ uint32_t cluster_rank() {
    uint32_t r; asm("mov.u32 %0, %%cluster_ctarank;" : "=r"(r)); return r;
}
#define CLUSTER_ARRIVE() asm volatile("barrier.cluster.arrive.aligned;" ::: "memory")
#define CLUSTER_WAIT()   asm volatile("barrier.cluster.wait.aligned;"   ::: "memory")

// horizontal dilations on an ST-strided window (counting stage)
__device__ __forceinline__ uint32_t hd3(const uint32_t* M, int r, int w) {
    uint32_t p = (w > 0)       ? M[r * ST + w - 1] : 0u;
    uint32_t c =                 M[r * ST + w];
    uint32_t n = (w < WPR - 1) ? M[r * ST + w + 1] : 0u;
    uint32_t v = c;
    v |= (c >> 1) | (n << 31); v |= (c << 1) | (p >> 31);
    v |= (c >> 2) | (n << 30); v |= (c << 2) | (p >> 30);
    v |= (c >> 3) | (n << 29); v |= (c << 3) | (p >> 29);
    return v;
}
__device__ __forceinline__ uint32_t hd2(const uint32_t* M, int r, int w) {
    uint32_t p = (w > 0)       ? M[r * ST + w - 1] : 0u;
    uint32_t c =                 M[r * ST + w];
    uint32_t n = (w < WPR - 1) ? M[r * ST + w + 1] : 0u;
    uint32_t v = c;
    v |= (c >> 1) | (n << 31); v |= (c << 1) | (p >> 31);
    v |= (c >> 2) | (n << 30); v |= (c << 2) | (p >> 30);
    return v;
}
__device__ __forceinline__ uint32_t dil3w(const uint32_t* M, int r, int w) {
    // squared radius 9: dy=0 -> |dx|<=3; |dy| in {1,2} -> |dx|<=2; |dy|=3 -> dx=0
    uint32_t v = hd3(M, r, w);
    v |= hd2(M, r - 1, w) | hd2(M, r + 1, w);
    v |= hd2(M, r - 2, w) | hd2(M, r + 2, w);
    v |= M[(r - 3) * ST + w] | M[(r + 3) * ST + w];
    return v;
}

// ---------------------------------------------------------------------------
// Fused kernel: binarize + Zhang-Suen to convergence (4-CTA cluster per
// image; cluster barrier split arrive/wait with interior rows computed
// inside the wait window), then parallel per-strip counting after a
// per-batch spin rendezvous.
// ---------------------------------------------------------------------------
__global__ void __launch_bounds__(NTHR, 1) __cluster_dims__(CSIZE, 1, 1)
skel_kernel(const float* __restrict__ pred, const float* __restrict__ gt,
            float* __restrict__ out) {
    __shared__ uint32_t bufs[2][BR * ST];
    __shared__ int s_chg[2][BR];     // stamp of last change per row, by parity
    __shared__ int s_changed;        // local: max stamp with any removal
    __shared__ int c_changed;        // cluster: max stamp with any removal
    __shared__ int stp, sfp, sfn;

    const int tid = threadIdx.x;
    const uint32_t rank = cluster_rank();
    const int img = blockIdx.x >> 2;
    const int b = img & 15;
    const int m = img >> 4;          // 0 = pred, 1 = gt
    const float* in = (m ? gt : pred) + (size_t)b * Hn * Wn + (size_t)rank * CROWS * Wn;

    // init stamps, flags, halo rows (halos stay 0 forever on image edges)
    if (tid < BR) { s_chg[0][tid] = 0; s_chg[1][tid] = 0; }
    if (tid == 0) { s_changed = 0; c_changed = 0; }
    if (tid < 2 * 2 * WPR) {          // 64 halo words: 2 bufs x {row 0, row BR-1}
        int bi = tid >> 5, r = (tid >> 4) & 1, w = tid & 15;
        bufs[bi][(r ? (BR - 1) : 0) * ST + w] = 0;
    }

    // --- binarize own 128 rows into bufs[0] (warp ballots -> packed words) ---
    #pragma unroll 4
    for (int p = 0; p < (CROWS * Wn) / NTHR; ++p) {
        int idx = p * NTHR + tid;
        float v = in[idx];
        uint32_t bits = __ballot_sync(0xffffffffu, v > 0.5f);
        if ((tid & 31) == 0) {
            int r = idx >> 9;            // local row
            int w = (idx >> 5) & 15;
            bufs[0][(r + 1) * ST + w] = bits;
        }
    }
    __syncthreads();

    const int lrow  = tid >> 3;          // 0..127
    const int q     = tid & 7;
    const int wbase = q * WPT;
    const int i     = lrow + 1;          // buffer row index (1..128)
    const bool topB = (lrow == 0)        && (rank > 0);
    const bool botB = (lrow == CROWS-1)  && (rank < CSIZE - 1);
    const bool interior = (lrow > 0) && (lrow < CROWS - 1);

    uint32_t R[WPT];
    #pragma unroll
    for (int w = 0; w < WPT; ++w) R[w] = bufs[0][i * ST + wbase + w];

    int s = 0;
    int myLast = 0;

    // one Zhang-Suen sub-step on this thread's 2 words; updates R + stamps
    auto compute_row = [&](int sub, const uint32_t* cur) {
        const uint32_t* rU = &cur[(i - 1) * ST];
        const uint32_t* rO = &cur[i * ST];
        const uint32_t* rD = &cur[(i + 1) * ST];

        uint32_t aP = wbase ? rU[wbase - 1] : 0u;
        uint32_t cP = wbase ? rO[wbase - 1] : 0u;
        uint32_t bP = wbase ? rD[wbase - 1] : 0u;
        uint32_t aC = rU[wbase];
        uint32_t cC = R[0];
        uint32_t bC = rD[wbase];
        uint32_t cRight = (q < 7) ? rO[wbase + WPT] : 0u;

        uint32_t removed = 0;
        uint32_t nR[WPT];
        #pragma unroll
        for (int w = 0; w < WPT; ++w) {
            const int gw = wbase + w;
            uint32_t aN = 0, bN = 0, cN;
            if (gw < WPR - 1) { aN = rU[gw + 1]; bN = rD[gw + 1]; }
            cN = (w < WPT - 1) ? R[w + 1] : cRight;

            // P2..P9 clockwise from North (funnel shifts)
            uint32_t n0 = aC;
            uint32_t n1 = __funnelshift_r(aC, aN, 1);
            uint32_t n2 = __funnelshift_r(cC, cN, 1);
            uint32_t n3 = __funnelshift_r(bC, bN, 1);
            uint32_t n4 = bC;
            uint32_t n5 = __funnelshift_l(bP, bC, 1);
            uint32_t n6 = __funnelshift_l(cP, cC, 1);
            uint32_t n7 = __funnelshift_l(aP, aC, 1);

            // 0->1 transitions
            uint32_t e0 = ~n0 & n1, e1 = ~n1 & n2, e2 = ~n2 & n3, e3 = ~n3 & n4;
            uint32_t e4 = ~n4 & n5, e5 = ~n5 & n6, e6 = ~n6 & n7, e7 = ~n7 & n0;
            // A == 1 via CSA: T = ss + 2*t + 4*D ; T==1 <=> ss & !(t|cc|tc)
            uint32_t as1, ac1, as2, ac2, as3, ac3, ass, asc, acs, acc, at, atc;
            FA(as1, ac1, e0, e1, e2);
            FA(as2, ac2, e3, e4, e5);
            as3 = e6 ^ e7; ac3 = e6 & e7;
            FA(ass, asc, as1, as2, as3);
            FA(acs, acc, ac1, ac2, ac3);
            at = asc ^ acs; atc = asc & acs;
            uint32_t A1 = ass & ~(at | acc | atc);

            // Bn via CSA: count = pss + 2*bt + 4*(btc+pcc)
            uint32_t p1, q1, p2, q2, p3, q3, pss, psc, pcs, pcc, bt, btc;
            FA(p1, q1, n0, n1, n2);
            FA(p2, q2, n3, n4, n5);
            p3 = n6 ^ n7; q3 = n6 & n7;
            FA(pss, psc, p1, p2, p3);
            FA(pcs, pcc, q1, q2, q3);
            bt = psc ^ pcs; btc = psc & pcs;
            uint32_t ge2 = bt | pcc | btc;                       // count >= 2
            uint32_t uu  = bt & pss;
            uint32_t ge7 = (pcc & btc) | ((pcc ^ btc) & uu);     // count >= 7

            uint32_t cond = A1 & ge2 & ~ge7;
            uint32_t x1, x2;
            if (sub == 0) { x1 = n0 & n2 & n4; x2 = n2 & n4 & n6; }
            else          { x1 = n0 & n2 & n6; x2 = n0 & n4 & n6; }
            cond &= ~(x1 | x2);

            removed |= cC & cond;
            nR[w] = cC & ~cond;

            aP = aC; aC = aN;
            cP = cC; cC = cN;
            bP = bC; bC = bN;
        }
        #pragma unroll
        for (int w = 0; w < WPT; ++w) R[w] = nR[w];
        if (removed) {
            s_chg[s & 1][i] = s;
            s_changed = s;
            myLast = s;
        }
    };

    for (;;) {
        ++s;
        uint32_t* cur = bufs[s & 1];
        __syncthreads();                 // (A) order prior compute's s_chg writes

        // ---- store phase ----
        if (myLast > s - 3) {
            #pragma unroll
            for (int w = 0; w < WPT; ++w) cur[i * ST + wbase + w] = R[w];
            if (topB) {
                #pragma unroll
                for (int w = 0; w < WPT; ++w)
                    st_cluster(smem_u32(&cur[(BR - 1) * ST + wbase + w]), rank - 1, R[w]);
            }
            if (botB) {
                #pragma unroll
                for (int w = 0; w < WPT; ++w)
                    st_cluster(smem_u32(&cur[0 * ST + wbase + w]), rank + 1, R[w]);
            }
        }
        // transmit own-row stamp of previous sub-iteration to neighbor halo
        if (q == 0) {
            const int pp0 = (s - 1) & 1;
            int stamp = s_chg[pp0][i];
            if (topB) st_cluster(smem_u32(&s_chg[pp0][BR - 1]), rank - 1, (uint32_t)stamp);
            if (botB) st_cluster(smem_u32(&s_chg[pp0][0]),      rank + 1, (uint32_t)stamp);
        }
        // broadcast "changed at s-1" to all CTAs of the cluster
        if (tid == 0 && s_changed == s - 1) {
            uint32_t a = smem_u32(&c_changed);
            #pragma unroll
            for (int c = 0; c < CSIZE; ++c) st_cluster(a, c, (uint32_t)(s - 1));
        }
        __syncthreads();                 // (A2) cur fully written CTA-locally
        CLUSTER_ARRIVE();

        const int pb = (s - 1) & 1, ps = s - 1;
        const int sub = (s + 1) & 1;     // s odd -> sub 0 ; s even -> sub 1

        // ---- interior rows: no halo dependence, compute inside wait window ----
        if (interior) {
            bool dirty = (s_chg[pb][i] == ps) | (s_chg[pb][i - 1] == ps) | (s_chg[pb][i + 1] == ps);
            if (dirty) compute_row(sub, cur);
        }

        CLUSTER_WAIT();                  // halo data/stamps/c_changed now visible

        if (c_changed <= s - 3) break;   // no removal in sub-iters s-1, s-2

        // ---- boundary rows (lrow 0 / CROWS-1): need remote halo ----
        if (!interior) {
            bool dirty = (s_chg[pb][i] == ps) | (s_chg[pb][i - 1] == ps) | (s_chg[pb][i + 1] == ps);
            if (dirty) compute_row(sub, cur);
        }
    }

    // ---- write out bit-packed skeleton from registers ----
    const int grow = (int)rank * CROWS + lrow;
    #pragma unroll
    for (int w = 0; w < WPT; ++w)
        g_skel[m][b][grow][wbase + w] = R[w];

    // ---- per-batch rendezvous (8 CTAs per batch) ----
    __threadfence();
    __syncthreads();
    if (tid == 0) {
        if (m == 0 && rank == 0) {
            g_counts[b][0] = 0; g_counts[b][1] = 0; g_counts[b][2] = 0;
            __threadfence();
        }
        atomicAdd(&g_bt[b], 1);
        while ((((volatile int*)g_bt)[b] & 7) != 0) __nanosleep(64);
        __threadfence();
    }
    __syncthreads();

    // ---- parallel counting: this CTA counts a 64-row strip of batch b ----
    const int cidx = m * CSIZE + (int)rank;     // 0..7
    const int base = cidx * STRIP - 3;
    uint32_t* sP = &bufs[0][0];                 // reuse smem (CR*ST <= BR*ST)
    uint32_t* sG = &bufs[1][0];
    const uint32_t* P = &g_skel[0][b][0][0];
    const uint32_t* G = &g_skel[1][b][0][0];

    for (int idx = tid; idx < CR * WPR; idx += NTHR) {
        int r = idx >> 4, w = idx & 15;
        int gr = base + r;
        bool ok = (gr >= 0) & (gr < Hn);
        sP[r * ST + w] = ok ? P[gr * WPR + w] : 0u;
        sG[r * ST + w] = ok ? G[gr * WPR + w] : 0u;
    }
    __syncthreads();

    // 64 rows x 16 words = 1024 elements: exactly one per thread
    const int rl = (tid >> 4) + 3;
    const int wc = tid & 15;
    uint32_t dg = dil3w(sG, rl, wc);
    uint32_t dp = dil3w(sP, rl, wc);
    uint32_t pw = sP[rl * ST + wc];
    uint32_t gw = sG[rl * ST + wc];
    int tp = __popc(pw & dg);
    int fp = __popc(pw & ~dg);
    int fn = __popc(gw & ~dp);

    if (tid == 0) { stp = 0; sfp = 0; sfn = 0; }
    __syncthreads();
    #pragma unroll
    for (int o = 16; o > 0; o >>= 1) {
        tp += __shfl_down_sync(0xffffffffu, tp, o);
        fp += __shfl_down_sync(0xffffffffu, fp, o);
        fn += __shfl_down_sync(0xffffffffu, fn, o);
    }
    if ((tid & 31) == 0) {
        atomicAdd(&stp, tp);
        atomicAdd(&sfp, fp);
        atomicAdd(&sfn, fn);
    }
    __syncthreads();

    if (tid == 0) {
        atomicAdd(&g_counts[b][0], stp);
        atomicAdd(&g_counts[b][1], sfp);
        atomicAdd(&g_counts[b][2], sfn);
        __threadfence();
        int t = atomicAdd(&g_ticket, 1) & 127;   // 128 CTAs total
        if (t == 127) {                           // last CTA finalizes
            __threadfence();
            float s0 = 0.f, s1 = 0.f, s2 = 0.f;
            for (int bb = 0; bb < BATCH; ++bb) {
                float TP = (float)g_counts[bb][0];
                float FP = (float)g_counts[bb][1];
                float FN = (float)g_counts[bb][2];
                s0 += TP / (TP + FP + 1e-12f);
                s1 += TP / (TP + FN + 1e-12f);
                s2 += TP / (TP + FP + FN + 1e-12f);
            }
            out[0] = s0 * (1.0f / BATCH);
            out[1] = s1 * (1.0f / BATCH);
            out[2] = s2 * (1.0f / BATCH);
        }
    }
}

extern "C" void kernel_launch(void* const* d_in, const int* in_sizes, int n_in,
                              void* d_out, int out_size) {
    (void)in_sizes; (void)n_in; (void)out_size;
    const float* pred = (const float*)d_in[0];
    const float* gt   = (const float*)d_in[1];
    skel_kernel<<<2 * BATCH * CSIZE, NTHR>>>(pred, gt, (float*)d_out);
}